// round 14
// baseline (speedup 1.0000x reference)
#include <cuda_runtime.h>
#include <cuda_bf16.h>
#include <cstdint>

// ---------------------------------------------------------------------------
// CrossAttention: B=8, Nt=1024, N=1024, D=768, H=8, HD=96, CLS=20, L=1044
// Round-13 base (878.7us) + direct-packed epilogues:
//  - Wq gemm writes g_qh (scaled, hi-packed) directly; g_q eliminated
//  - Wkv k-half CTAs write g_kh directly; v-half still fp32 -> prep_v
//  - prep shrinks to V-only transpose/split
// ---------------------------------------------------------------------------

#define DEV_INLINE __device__ __forceinline__

constexpr int   Bsz  = 8;
constexpr int   NtQ  = 1024;
constexpr int   Dm   = 768;
constexpr float QSCALE = 0.10206207261596577f;   // 96^-0.5

// ---------------- scratch (static device globals; no allocation) -----------
__device__ float    g_kv [Bsz * NtQ * 2 * Dm];      // 50 MB (v-half used)
__device__ float    g_ao [Bsz * NtQ * Dm];          // 25 MB
// attention operands (head-major); q/k hi-only
__device__ uint32_t g_qh [64 * 1024 * 48];
__device__ uint32_t g_kh [64 * 1024 * 48];
__device__ uint32_t g_vth[64 * 96 * 512];
__device__ uint32_t g_vtl[64 * 96 * 512];
__device__ uint32_t g_mask[64 * 1024 * 32];         // 8.4 MB keep-bitmask

// ---------------------------------------------------------------------------
DEV_INLINE void split2(float x, float y, uint32_t& hi, uint32_t& lo) {
    __nv_bfloat162 h = __floats2bfloat162_rn(x, y);
    float hx = __bfloat162float(h.x), hy = __bfloat162float(h.y);
    __nv_bfloat162 l = __floats2bfloat162_rn(x - hx, y - hy);
    hi = *reinterpret_cast<uint32_t*>(&h);
    lo = *reinterpret_cast<uint32_t*>(&l);
}
DEV_INLINE uint32_t pack_hi(float x, float y) {
    __nv_bfloat162 h = __floats2bfloat162_rn(x, y);
    return *reinterpret_cast<uint32_t*>(&h);
}

DEV_INLINE void mma16816(float* d, const uint32_t* a, const uint32_t* b) {
    asm volatile(
        "mma.sync.aligned.m16n8k16.row.col.f32.bf16.bf16.f32 "
        "{%0,%1,%2,%3}, {%4,%5,%6,%7}, {%8,%9}, {%0,%1,%2,%3};"
        : "+f"(d[0]), "+f"(d[1]), "+f"(d[2]), "+f"(d[3])
        : "r"(a[0]), "r"(a[1]), "r"(a[2]), "r"(a[3]), "r"(b[0]), "r"(b[1]));
}

DEV_INLINE uint32_t smem_u32(const void* p) {
    uint32_t a;
    asm("{ .reg .u64 t; cvta.to.shared.u64 t, %1; cvt.u32.u64 %0, t; }"
        : "=r"(a) : "l"(p));
    return a;
}
DEV_INLINE void ldsm4(uint32_t* r, uint32_t a) {
    asm volatile("ldmatrix.sync.aligned.m8n8.x4.shared.b16 {%0,%1,%2,%3}, [%4];"
                 : "=r"(r[0]), "=r"(r[1]), "=r"(r[2]), "=r"(r[3]) : "r"(a));
}
DEV_INLINE void ldsm2(uint32_t* r, uint32_t a) {
    asm volatile("ldmatrix.sync.aligned.m8n8.x2.shared.b16 {%0,%1}, [%2];"
                 : "=r"(r[0]), "=r"(r[1]) : "r"(a));
}

DEV_INLINE uint32_t rotl32(uint32_t x, int d) { return __funnelshift_l(x, x, d); }

// JAX threefry2x32, key (0,42), partitionable: counter (0, fi), out = x0^x1
DEV_INLINE uint32_t tf_bits(uint32_t fi) {
    const uint32_t ks1 = 42u, ks2 = 0x1BD11BF0u;
    uint32_t x0 = 0u, x1 = fi + ks1;
    x0 += x1; x1 = rotl32(x1, 13); x1 ^= x0;
    x0 += x1; x1 = rotl32(x1, 15); x1 ^= x0;
    x0 += x1; x1 = rotl32(x1, 26); x1 ^= x0;
    x0 += x1; x1 = rotl32(x1,  6); x1 ^= x0;
    x0 += ks1; x1 += ks2 + 1u;
    x0 += x1; x1 = rotl32(x1, 17); x1 ^= x0;
    x0 += x1; x1 = rotl32(x1, 29); x1 ^= x0;
    x0 += x1; x1 = rotl32(x1, 16); x1 ^= x0;
    x0 += x1; x1 = rotl32(x1, 24); x1 ^= x0;
    x0 += ks2; x1 += 2u;
    x0 += x1; x1 = rotl32(x1, 13); x1 ^= x0;
    x0 += x1; x1 = rotl32(x1, 15); x1 ^= x0;
    x0 += x1; x1 = rotl32(x1, 26); x1 ^= x0;
    x0 += x1; x1 = rotl32(x1,  6); x1 ^= x0;
    x1 += ks1 + 3u;
    x0 += x1; x1 = rotl32(x1, 17); x1 ^= x0;
    x0 += x1; x1 = rotl32(x1, 29); x1 ^= x0;
    x0 += x1; x1 = rotl32(x1, 16); x1 ^= x0;
    x0 += x1; x1 = rotl32(x1, 24); x1 ^= x0;
    x0 += ks1; x1 += ks2 + 4u;
    x0 += x1; x1 = rotl32(x1, 13); x1 ^= x0;
    x0 += x1; x1 = rotl32(x1, 15); x1 ^= x0;
    x0 += x1; x1 = rotl32(x1, 26); x1 ^= x0;
    x0 += x1; x1 = rotl32(x1,  6); x1 ^= x0;
    x0 += ks2; x1 += 5u;
    return x0 ^ x1;
}

// w = (bh*1024 + q)*32 + wi ; bit j (keep=1) for col wi*32+j
DEV_INLINE uint32_t mask_word(uint32_t w) {
    const uint32_t bh = w >> 15;
    const uint32_t rest = w & 32767u;
    const uint32_t q = rest >> 5, wi = rest & 31u;
    const uint32_t fi0 = (bh * 1044u + 20u + q) * 1024u + wi * 32u;
    uint32_t bits = 0u;
#pragma unroll 4
    for (int j = 0; j < 32; j++) {
        uint32_t b = tf_bits(fi0 + (uint32_t)j);
        bits |= ((b >> 9) >= 2516583u ? 1u : 0u) << j;
    }
    return bits;
}

// ===========================================================================
//  mma.sync GEMM (round-11 core) with selectable epilogue:
//   mode 0: plain fp32 C write (+bias)
//   mode 1: pack_hi(acc*QSCALE) -> g_qh head-major (q projection)
//   mode 2: bx<6 -> pack_hi(acc) -> g_kh ; bx>=6 -> plain C (v-half, Wkv)
// ===========================================================================
constexpr int SSTR = 20;

template<bool BIAS>
__global__ __launch_bounds__(256, 2) void mma_gemm(
    const float* __restrict__ A, const float* __restrict__ Bm,
    const float* __restrict__ bias, float* __restrict__ C,
    int M, int N, int K,
    uint32_t mw_start, uint32_t mw_end, uint32_t mw_stride, int mode)
{
    __shared__ uint32_t Ah[128 * SSTR];
    __shared__ uint32_t Al[128 * SSTR];
    __shared__ uint32_t Bh[128 * SSTR];
    __shared__ uint32_t Bl[128 * SSTR];

    const int tid  = threadIdx.x;
    const int lane = tid & 31;
    const int wid  = tid >> 5;
    const int wy   = wid >> 2;
    const int wx   = wid & 3;

    const int m0 = blockIdx.y * 128;
    const int n0 = blockIdx.x * 128;
    const uint32_t gid =
        ((uint32_t)blockIdx.y * gridDim.x + blockIdx.x) * 256u + (uint32_t)tid;

    const int lt = lane >> 3, lr = lane & 7;
    const int a_row = ((lt & 1) << 3) + lr;
    const int a_cw  = (lt >> 1) << 2;
    const int b_row = lr;
    const int b_cw  = ((lane >> 3) & 1) << 2;

    const uint32_t ahb = smem_u32(Ah), alb = smem_u32(Al);
    const uint32_t bhb = smem_u32(Bh), blb = smem_u32(Bl);

    float acc[4][4][4];
#pragma unroll
    for (int i = 0; i < 4; i++)
#pragma unroll
        for (int j = 0; j < 4; j++)
#pragma unroll
            for (int q = 0; q < 4; q++) acc[i][j][q] = 0.f;

    const int gq = lane >> 2;
    const int gt = lane & 3;

    for (int kc = 0; kc < K; kc += 32) {
        __syncthreads();
        // ---- A chunk [128m x 32k] ----
#pragma unroll
        for (int p = 0; p < 4; p++) {
            const int idx = tid + p * 256;
            const int row = idx >> 3, c4 = idx & 7;
            float4 v = *reinterpret_cast<const float4*>(
                A + (size_t)(m0 + row) * K + kc + c4 * 4);
            uint32_t h01, l01, h23, l23;
            split2(v.x, v.y, h01, l01);
            split2(v.z, v.w, h23, l23);
            const int w = row * SSTR + c4 * 2;
            Ah[w] = h01; Ah[w + 1] = h23;
            Al[w] = l01; Al[w + 1] = l23;
        }
        // ---- B chunk transposed: Bt[n][k] ----
        {
            const int n  = tid & 127;
            const int kq = tid >> 7;
            const float* Bg = Bm + (size_t)kc * N + n0 + n;
#pragma unroll
            for (int p = 0; p < 8; p++) {
                const int k = kq * 16 + p * 2;
                float x = Bg[(size_t)k * N];
                float y = Bg[(size_t)(k + 1) * N];
                uint32_t h, l;
                split2(x, y, h, l);
                const int w = n * SSTR + k / 2;
                Bh[w] = h; Bl[w] = l;
            }
        }
        // ---- fused mask generation ----
        if (mw_stride) {
            const uint32_t w = mw_start + gid + (uint32_t)(kc >> 5) * mw_stride;
            if (w < mw_end) g_mask[w] = mask_word(w);
        }
        __syncthreads();

#pragma unroll
        for (int ks = 0; ks < 2; ks++) {
            uint32_t ah[4][4], al[4][4];
#pragma unroll
            for (int mt = 0; mt < 4; mt++) {
                const uint32_t off =
                    (uint32_t)(((wy * 64 + mt * 16 + a_row) * SSTR) + ks * 8 + a_cw) * 4u;
                ldsm4(ah[mt], ahb + off);
                ldsm4(al[mt], alb + off);
            }
#pragma unroll
            for (int nt = 0; nt < 4; nt++) {
                const uint32_t off =
                    (uint32_t)(((wx * 32 + nt * 8 + b_row) * SSTR) + ks * 8 + b_cw) * 4u;
                uint32_t bh[2], bl[2];
                ldsm2(bh, bhb + off);
                ldsm2(bl, blb + off);
#pragma unroll
                for (int mt = 0; mt < 4; mt++) {
                    mma16816(acc[mt][nt], ah[mt], bh);
                    mma16816(acc[mt][nt], ah[mt], bl);
                    mma16816(acc[mt][nt], al[mt], bh);
                }
            }
        }
    }

    // ---- epilogue ----
    const bool kpack = (mode == 1) || (mode == 2 && n0 < 768);
    if (kpack) {
        uint32_t* dst = (mode == 1) ? g_qh : g_kh;
        const float sc = (mode == 1) ? QSCALE : 1.0f;
#pragma unroll
        for (int mt = 0; mt < 4; mt++) {
            const int r0g = m0 + wy * 64 + mt * 16 + gq;
            const int b = r0g >> 10, rin = r0g & 1023;
#pragma unroll
            for (int nt = 0; nt < 4; nt++) {
                const int col = n0 + wx * 32 + nt * 8 + gt * 2;
                const int hh = col / 96, d = col - hh * 96;
                const size_t base =
                    ((size_t)(b * 8 + hh) * 1024 + rin) * 48 + (d >> 1);
                dst[base] = pack_hi(acc[mt][nt][0] * sc, acc[mt][nt][1] * sc);
                dst[base + (size_t)8 * 48] =
                    pack_hi(acc[mt][nt][2] * sc, acc[mt][nt][3] * sc);
            }
        }
    } else {
#pragma unroll
        for (int mt = 0; mt < 4; mt++) {
            const int r0 = m0 + wy * 64 + mt * 16 + gq;
#pragma unroll
            for (int nt = 0; nt < 4; nt++) {
                const int col = n0 + wx * 32 + nt * 8 + gt * 2;
                float bx = 0.f, by = 0.f;
                if (BIAS) { bx = bias[col]; by = bias[col + 1]; }
                *reinterpret_cast<float2*>(C + (size_t)r0 * N + col) =
                    make_float2(acc[mt][nt][0] + bx, acc[mt][nt][1] + by);
                *reinterpret_cast<float2*>(C + (size_t)(r0 + 8) * N + col) =
                    make_float2(acc[mt][nt][2] + bx, acc[mt][nt][3] + by);
            }
        }
    }
}

// ===========================================================================
//  prep_v: transpose+split V only (q/k now packed by the gemm epilogues)
// ===========================================================================
__global__ __launch_bounds__(256) void prep_v()
{
    __shared__ float vs[64 * 100];
    const int nt = blockIdx.x, bh = blockIdx.y;
    const int b = bh >> 3, h = bh & 7;
    const int tid = threadIdx.x;
    const int n0 = nt * 64;

#pragma unroll
    for (int p = 0; p < 6; p++) {
        const int idx = tid + p * 256;
        const int row = idx / 24, c4 = idx % 24;
        const size_t grow = (size_t)(b * 1024 + n0 + row);
        float4 vv = *reinterpret_cast<const float4*>(
            g_kv + grow * 1536 + 768 + h * 96 + c4 * 4);
        *reinterpret_cast<float4*>(&vs[row * 100 + c4 * 4]) = vv;
    }
    __syncthreads();
#pragma unroll
    for (int p = 0; p < 12; p++) {
        const int idx = tid + p * 256;
        const int d = idx >> 5, nw = idx & 31;
        float v0 = vs[(2 * nw) * 100 + d];
        float v1 = vs[(2 * nw + 1) * 100 + d];
        uint32_t hh, ll;
        split2(v0, v1, hh, ll);
        const size_t w = (size_t)(bh * 96 + d) * 512 + nt * 32 + nw;
        g_vth[w] = hh; g_vtl[w] = ll;
    }
}

// ===========================================================================
//  fused attention (round-12/13): QK hi-only both passes; PV 3-term.
// ===========================================================================
constexpr int QSTR = 52;
constexpr int VSTR = 36;

DEV_INLINE void qk_mma_hi(uint32_t qhb, uint32_t khb,
                          int rowb, int lane, float (*sacc)[4])
{
    const int lt = lane >> 3, lr = lane & 7;
    const int a_row = ((lt & 1) << 3) + lr;
    const int a_cw  = (lt >> 1) << 2;
    const int b_row = lr;
    const int b_cw  = ((lane >> 3) & 1) << 2;
#pragma unroll
    for (int i = 0; i < 8; i++)
#pragma unroll
        for (int j = 0; j < 4; j++) sacc[i][j] = 0.f;
#pragma unroll
    for (int ks = 0; ks < 6; ks++) {
        uint32_t ah[4];
        const uint32_t aoff =
            (uint32_t)(((rowb + a_row) * QSTR) + ks * 8 + a_cw) * 4u;
        ldsm4(ah, qhb + aoff);
#pragma unroll
        for (int nt = 0; nt < 8; nt++) {
            const uint32_t boff =
                (uint32_t)(((nt * 8 + b_row) * QSTR) + ks * 8 + b_cw) * 4u;
            uint32_t bh2[2];
            ldsm2(bh2, khb + boff);
            mma16816(sacc[nt], ah, bh2);
        }
    }
}

DEV_INLINE void online_upd(float& m, float& z, float s) {
    float nm = fmaxf(m, s);
    z = z * __expf(m - nm) + __expf(s - nm);
    m = nm;
}
DEV_INLINE void comb_mz(float& m, float& z, int d) {
    float mo = __shfl_xor_sync(0xffffffffu, m, d);
    float zo = __shfl_xor_sync(0xffffffffu, z, d);
    float nm = fmaxf(m, mo);
    z = z * __expf(m - nm) + zo * __expf(mo - nm);
    m = nm;
}

__global__ __launch_bounds__(256, 2) void attn_mma()
{
    extern __shared__ uint32_t smw[];
    uint32_t* Qh = smw;
    uint32_t* Kh = Qh + 128 * QSTR;
    uint32_t* Vh = Kh + 64 * QSTR;
    uint32_t* Vl = Vh + 96 * VSTR;

    const int qt = blockIdx.x, bh = blockIdx.y;
    const int b = bh >> 3, h = bh & 7;
    const int tid = threadIdx.x, lane = tid & 31, wid = tid >> 5;
    const int gq = lane >> 2, gt = lane & 3;
    const int rowb = wid * 16;

    const uint32_t qhb = smem_u32(Qh);
    const uint32_t khb = smem_u32(Kh);
    const uint32_t vhb = smem_u32(Vh), vlb = smem_u32(Vl);

    {
        const uint4* qh4 = reinterpret_cast<const uint4*>(g_qh + (size_t)(bh * 1024 + qt * 128) * 48);
#pragma unroll
        for (int p = 0; p < 6; p++) {
            const int idx = tid + p * 256;
            const int row = idx / 12, s = idx % 12;
            *reinterpret_cast<uint4*>(&Qh[row * QSTR + s * 4]) = qh4[row * 12 + s];
        }
    }

    float m1[2] = {-1e30f, -1e30f}, z1[2] = {0.f, 0.f};
    float m2[2] = {-1e30f, -1e30f}, z2[2] = {0.f, 0.f};
    float sacc[8][4];

    // ---- PASS A: stats ----
    for (int c = 0; c < 16; c++) {
        __syncthreads();
        {
            const uint4* kh4 = reinterpret_cast<const uint4*>(g_kh + (size_t)(bh * 1024 + c * 64) * 48);
#pragma unroll
            for (int p = 0; p < 3; p++) {
                const int idx = tid + p * 256;
                const int row = idx / 12, s = idx % 12;
                *reinterpret_cast<uint4*>(&Kh[row * QSTR + s * 4]) = kh4[row * 12 + s];
            }
        }
        __syncthreads();
        qk_mma_hi(qhb, khb, rowb, lane, sacc);

        if (c == 0) {
#pragma unroll
            for (int nt = 0; nt < 8; nt++)
#pragma unroll
                for (int v = 0; v < 4; v++) {
                    const int col = nt * 8 + gt * 2 + (v & 1);
                    const int r = v >> 1;
                    if (col < 20) online_upd(m1[r], z1[r], sacc[nt][v]);
                    else          online_upd(m2[r], z2[r], sacc[nt][v]);
                }
        } else {
#pragma unroll
            for (int r = 0; r < 2; r++) {
                float lm = -1e30f;
#pragma unroll
                for (int nt = 0; nt < 8; nt++)
                    lm = fmaxf(lm, fmaxf(sacc[nt][r * 2], sacc[nt][r * 2 + 1]));
                const float nm = fmaxf(m2[r], lm);
                float zs = 0.f;
#pragma unroll
                for (int nt = 0; nt < 8; nt++)
                    zs += __expf(sacc[nt][r * 2] - nm) + __expf(sacc[nt][r * 2 + 1] - nm);
                z2[r] = z2[r] * __expf(m2[r] - nm) + zs;
                m2[r] = nm;
            }
        }
    }
#pragma unroll
    for (int r = 0; r < 2; r++) {
        comb_mz(m1[r], z1[r], 1); comb_mz(m1[r], z1[r], 2);
        comb_mz(m2[r], z2[r], 1); comb_mz(m2[r], z2[r], 2);
    }
    const float rz1[2] = {1.f / z1[0], 1.f / z1[1]};
    const float rz2[2] = {1.f / z2[0], 1.f / z2[1]};

    // ---- PASS B: hi-only QK recompute + mask + PV (3-term) ----
    float vacc[12][4];
#pragma unroll
    for (int i = 0; i < 12; i++)
#pragma unroll
        for (int j = 0; j < 4; j++) vacc[i][j] = 0.f;
    float zf[2] = {0.f, 0.f};
    const int q0 = qt * 128 + rowb + gq;
    const uint32_t* mrow = g_mask + ((size_t)(bh << 10) + q0) * 32;

    const int v_row = lane & 7;
    const int v_cw  = ((lane >> 3) & 1) << 2;

    for (int c = 0; c < 16; c++) {
        __syncthreads();
        {
            const uint4* kh4 = reinterpret_cast<const uint4*>(g_kh + (size_t)(bh * 1024 + c * 64) * 48);
#pragma unroll
            for (int p = 0; p < 3; p++) {
                const int idx = tid + p * 256;
                const int row = idx / 12, s = idx % 12;
                *reinterpret_cast<uint4*>(&Kh[row * QSTR + s * 4]) = kh4[row * 12 + s];
            }
            const uint4* vh4 = reinterpret_cast<const uint4*>(g_vth + (size_t)(bh * 96) * 512);
            const uint4* vl4 = reinterpret_cast<const uint4*>(g_vtl + (size_t)(bh * 96) * 512);
#pragma unroll
            for (int p = 0; p < 3; p++) {
                const int idx = tid + p * 256;
                const int row = idx >> 3, s = idx & 7;
                *reinterpret_cast<uint4*>(&Vh[row * VSTR + s * 4]) = vh4[row * 128 + c * 8 + s];
                *reinterpret_cast<uint4*>(&Vl[row * VSTR + s * 4]) = vl4[row * 128 + c * 8 + s];
            }
        }
        __syncthreads();
        qk_mma_hi(qhb, khb, rowb, lane, sacc);

        const uint32_t mw0 = mrow[c * 2];
        const uint32_t mw1 = mrow[c * 2 + 1];
        const uint32_t mw2 = mrow[8 * 32 + c * 2];
        const uint32_t mw3 = mrow[8 * 32 + c * 2 + 1];

#pragma unroll
        for (int ks = 0; ks < 4; ks++) {
            uint32_t pah[4], pal[4];
#pragma unroll
            for (int half = 0; half < 2; half++) {
                const int nt = 2 * ks + half;
                float e[4];
#pragma unroll
                for (int v = 0; v < 4; v++) {
                    const int co = nt * 8 + gt * 2 + (v & 1);
                    const int r = v >> 1;
                    const bool cls = (c == 0) && (co < 20);
                    const float m  = cls ? m1[r] : m2[r];
                    const float rz = cls ? rz1[r] : rz2[r];
                    const float a  = __expf(sacc[nt][v] - m) * rz;
                    const uint32_t wsel = (nt < 4) ? (r ? mw2 : mw0) : (r ? mw3 : mw1);
                    const uint32_t keep = (wsel >> (co & 31)) & 1u;
                    const float ev = keep ? __expf(a - 1.f) : 0.f;
                    e[v] = ev;
                    zf[r] += ev;
                }
                uint32_t hh, ll;
                split2(e[0], e[1], hh, ll);
                pah[half * 2] = hh;     pal[half * 2] = ll;
                split2(e[2], e[3], hh, ll);
                pah[half * 2 + 1] = hh; pal[half * 2 + 1] = ll;
            }
#pragma unroll
            for (int nt = 0; nt < 12; nt++) {
                const uint32_t off =
                    (uint32_t)(((nt * 8 + v_row) * VSTR) + ks * 8 + v_cw) * 4u;
                uint32_t bh2[2], bl2[2];
                ldsm2(bh2, vhb + off);
                ldsm2(bl2, vlb + off);
                mma16816(vacc[nt], pah, bh2);
                mma16816(vacc[nt], pah, bl2);
                mma16816(vacc[nt], pal, bh2);
            }
        }
    }

#pragma unroll
    for (int r = 0; r < 2; r++) {
        zf[r] += __shfl_xor_sync(0xffffffffu, zf[r], 1);
        zf[r] += __shfl_xor_sync(0xffffffffu, zf[r], 2);
    }
    const float r0 = 1.f / zf[0], r1 = 1.f / zf[1];
    float* og = g_ao + (size_t)(b * 1024 + q0) * 768 + h * 96;
#pragma unroll
    for (int nt = 0; nt < 12; nt++) {
        const int col = nt * 8 + gt * 2;
        *reinterpret_cast<float2*>(og + col) =
            make_float2(vacc[nt][0] * r0, vacc[nt][1] * r0);
        *reinterpret_cast<float2*>(og + 8 * 768 + col) =
            make_float2(vacc[nt][2] * r1, vacc[nt][3] * r1);
    }
}

// ---------------------------------------------------------------------------
extern "C" void kernel_launch(void* const* d_in, const int* in_sizes, int n_in,
                              void* d_out, int out_size)
{
    const float* input_query = (const float*)d_in[0];
    const float* input_key   = (const float*)d_in[1];
    const float* Wq          = (const float*)d_in[2];
    const float* Wkv         = (const float*)d_in[3];
    // d_in[4] = Wcls  -- provably unused
    const float* Wproj       = (const float*)d_in[5];
    const float* bproj       = (const float*)d_in[6];
    float* out = (float*)d_out;

    float *kvp, *aop;
    cudaGetSymbolAddress((void**)&kvp, g_kv);
    cudaGetSymbolAddress((void**)&aop, g_ao);

    const int attn_smem = (128 * QSTR + 64 * QSTR + 96 * VSTR * 2) * 4; // ~68KB
    cudaFuncSetAttribute(attn_mma, cudaFuncAttributeMaxDynamicSharedMemorySize, attn_smem);

    // q projection -> packs g_qh directly (mode 1); mask [0, 1048576)
    mma_gemm<false><<<dim3(6, 64), 256>>>(input_query, Wq, nullptr, nullptr,
                                          8192, 768, 768,
                                          0u, 1048576u, 98304u, 1);
    // kv projection -> k-half packs g_kh, v-half fp32 to g_kv (mode 2);
    // mask [1048576, 2097152)
    mma_gemm<false><<<dim3(12, 64), 256>>>(input_key, Wkv, nullptr, kvp,
                                           8192, 1536, 768,
                                           1048576u, 2097152u, 196608u, 2);
    prep_v<<<dim3(16, 64), 256>>>();
    attn_mma<<<dim3(8, 64), 256, attn_smem>>>();
    // out = attn_out @ Wproj + b (mode 0)
    mma_gemm<true><<<dim3(6, 64), 256>>>(aop, Wproj, bproj, out,
                                         8192, 768, 768,
                                         0u, 0u, 0u, 0);
}

// round 15
// speedup vs baseline: 1.0881x; 1.0881x over previous
#include <cuda_runtime.h>
#include <cuda_bf16.h>
#include <cstdint>

// ---------------------------------------------------------------------------
// CrossAttention: B=8, Nt=1024, N=1024, D=768, H=8, HD=96, CLS=20, L=1044
// Round-13 base (878.7us, best) + ONE change: Wq and Wkv fused into a single
// 1152-CTA launch (tail-wave elimination); mask emission re-spread across the
// fused grid (every 3rd iter). Attention/prep/Wproj unchanged.
// ---------------------------------------------------------------------------

#define DEV_INLINE __device__ __forceinline__

constexpr int   Bsz  = 8;
constexpr int   NtQ  = 1024;
constexpr int   Dm   = 768;
constexpr float QSCALE = 0.10206207261596577f;   // 96^-0.5

// ---------------- scratch (static device globals; no allocation) -----------
__device__ float    g_q  [Bsz * NtQ * Dm];          // 25 MB
__device__ float    g_kv [Bsz * NtQ * 2 * Dm];      // 50 MB
__device__ float    g_ao [Bsz * NtQ * Dm];          // 25 MB
// attention operands (head-major); q/k hi-only
__device__ uint32_t g_qh [64 * 1024 * 48];
__device__ uint32_t g_kh [64 * 1024 * 48];
__device__ uint32_t g_vth[64 * 96 * 512];
__device__ uint32_t g_vtl[64 * 96 * 512];
__device__ uint32_t g_mask[64 * 1024 * 32];         // 8.4 MB keep-bitmask

// ---------------------------------------------------------------------------
DEV_INLINE void split2(float x, float y, uint32_t& hi, uint32_t& lo) {
    __nv_bfloat162 h = __floats2bfloat162_rn(x, y);
    float hx = __bfloat162float(h.x), hy = __bfloat162float(h.y);
    __nv_bfloat162 l = __floats2bfloat162_rn(x - hx, y - hy);
    hi = *reinterpret_cast<uint32_t*>(&h);
    lo = *reinterpret_cast<uint32_t*>(&l);
}
DEV_INLINE uint32_t pack_hi(float x, float y) {
    __nv_bfloat162 h = __floats2bfloat162_rn(x, y);
    return *reinterpret_cast<uint32_t*>(&h);
}

DEV_INLINE void mma16816(float* d, const uint32_t* a, const uint32_t* b) {
    asm volatile(
        "mma.sync.aligned.m16n8k16.row.col.f32.bf16.bf16.f32 "
        "{%0,%1,%2,%3}, {%4,%5,%6,%7}, {%8,%9}, {%0,%1,%2,%3};"
        : "+f"(d[0]), "+f"(d[1]), "+f"(d[2]), "+f"(d[3])
        : "r"(a[0]), "r"(a[1]), "r"(a[2]), "r"(a[3]), "r"(b[0]), "r"(b[1]));
}

DEV_INLINE uint32_t smem_u32(const void* p) {
    uint32_t a;
    asm("{ .reg .u64 t; cvta.to.shared.u64 t, %1; cvt.u32.u64 %0, t; }"
        : "=r"(a) : "l"(p));
    return a;
}
DEV_INLINE void ldsm4(uint32_t* r, uint32_t a) {
    asm volatile("ldmatrix.sync.aligned.m8n8.x4.shared.b16 {%0,%1,%2,%3}, [%4];"
                 : "=r"(r[0]), "=r"(r[1]), "=r"(r[2]), "=r"(r[3]) : "r"(a));
}
DEV_INLINE void ldsm2(uint32_t* r, uint32_t a) {
    asm volatile("ldmatrix.sync.aligned.m8n8.x2.shared.b16 {%0,%1}, [%2];"
                 : "=r"(r[0]), "=r"(r[1]) : "r"(a));
}

DEV_INLINE uint32_t rotl32(uint32_t x, int d) { return __funnelshift_l(x, x, d); }

// JAX threefry2x32, key (0,42), partitionable: counter (0, fi), out = x0^x1
DEV_INLINE uint32_t tf_bits(uint32_t fi) {
    const uint32_t ks1 = 42u, ks2 = 0x1BD11BF0u;
    uint32_t x0 = 0u, x1 = fi + ks1;
    x0 += x1; x1 = rotl32(x1, 13); x1 ^= x0;
    x0 += x1; x1 = rotl32(x1, 15); x1 ^= x0;
    x0 += x1; x1 = rotl32(x1, 26); x1 ^= x0;
    x0 += x1; x1 = rotl32(x1,  6); x1 ^= x0;
    x0 += ks1; x1 += ks2 + 1u;
    x0 += x1; x1 = rotl32(x1, 17); x1 ^= x0;
    x0 += x1; x1 = rotl32(x1, 29); x1 ^= x0;
    x0 += x1; x1 = rotl32(x1, 16); x1 ^= x0;
    x0 += x1; x1 = rotl32(x1, 24); x1 ^= x0;
    x0 += ks2; x1 += 2u;
    x0 += x1; x1 = rotl32(x1, 13); x1 ^= x0;
    x0 += x1; x1 = rotl32(x1, 15); x1 ^= x0;
    x0 += x1; x1 = rotl32(x1, 26); x1 ^= x0;
    x0 += x1; x1 = rotl32(x1,  6); x1 ^= x0;
    x1 += ks1 + 3u;
    x0 += x1; x1 = rotl32(x1, 17); x1 ^= x0;
    x0 += x1; x1 = rotl32(x1, 29); x1 ^= x0;
    x0 += x1; x1 = rotl32(x1, 16); x1 ^= x0;
    x0 += x1; x1 = rotl32(x1, 24); x1 ^= x0;
    x0 += ks1; x1 += ks2 + 4u;
    x0 += x1; x1 = rotl32(x1, 13); x1 ^= x0;
    x0 += x1; x1 = rotl32(x1, 15); x1 ^= x0;
    x0 += x1; x1 = rotl32(x1, 26); x1 ^= x0;
    x0 += x1; x1 = rotl32(x1,  6); x1 ^= x0;
    x0 += ks2; x1 += 5u;
    return x0 ^ x1;
}

// w = (bh*1024 + q)*32 + wi ; bit j (keep=1) for col wi*32+j
DEV_INLINE uint32_t mask_word(uint32_t w) {
    const uint32_t bh = w >> 15;
    const uint32_t rest = w & 32767u;
    const uint32_t q = rest >> 5, wi = rest & 31u;
    const uint32_t fi0 = (bh * 1044u + 20u + q) * 1024u + wi * 32u;
    uint32_t bits = 0u;
#pragma unroll 4
    for (int j = 0; j < 32; j++) {
        uint32_t b = tf_bits(fi0 + (uint32_t)j);
        bits |= ((b >> 9) >= 2516583u ? 1u : 0u) << j;
    }
    return bits;
}

// ===========================================================================
//  shared gemm tile body (round-13 core): 3-term split, ldmatrix, fused mask
// ===========================================================================
constexpr int SSTR = 20;

DEV_INLINE void gemm_body(
    const float* __restrict__ A, const float* __restrict__ Bm,
    const float* __restrict__ bias, float* __restrict__ C,
    int N, int K, int m0, int n0, int tid,
    uint32_t gid, uint32_t mw_stride, uint32_t mw_total, int mw_every,
    uint32_t* Ah, uint32_t* Al, uint32_t* Bh, uint32_t* Bl, bool has_bias)
{
    const int lane = tid & 31;
    const int wid  = tid >> 5;
    const int wy   = wid >> 2;
    const int wx   = wid & 3;

    const int lt = lane >> 3, lr = lane & 7;
    const int a_row = ((lt & 1) << 3) + lr;
    const int a_cw  = (lt >> 1) << 2;
    const int b_row = lr;
    const int b_cw  = ((lane >> 3) & 1) << 2;

    const uint32_t ahb = smem_u32(Ah), alb = smem_u32(Al);
    const uint32_t bhb = smem_u32(Bh), blb = smem_u32(Bl);

    float acc[4][4][4];
#pragma unroll
    for (int i = 0; i < 4; i++)
#pragma unroll
        for (int j = 0; j < 4; j++)
#pragma unroll
            for (int q = 0; q < 4; q++) acc[i][j][q] = 0.f;

    const int gq = lane >> 2;
    const int gt = lane & 3;

    for (int kc = 0; kc < K; kc += 32) {
        __syncthreads();
        // ---- A chunk [128m x 32k] ----
#pragma unroll
        for (int p = 0; p < 4; p++) {
            const int idx = tid + p * 256;
            const int row = idx >> 3, c4 = idx & 7;
            float4 v = *reinterpret_cast<const float4*>(
                A + (size_t)(m0 + row) * K + kc + c4 * 4);
            uint32_t h01, l01, h23, l23;
            split2(v.x, v.y, h01, l01);
            split2(v.z, v.w, h23, l23);
            const int w = row * SSTR + c4 * 2;
            Ah[w] = h01; Ah[w + 1] = h23;
            Al[w] = l01; Al[w + 1] = l23;
        }
        // ---- B chunk transposed: Bt[n][k] ----
        {
            const int n  = tid & 127;
            const int kq = tid >> 7;
            const float* Bg = Bm + (size_t)kc * N + n0 + n;
#pragma unroll
            for (int p = 0; p < 8; p++) {
                const int k = kq * 16 + p * 2;
                float x = Bg[(size_t)k * N];
                float y = Bg[(size_t)(k + 1) * N];
                uint32_t h, l;
                split2(x, y, h, l);
                const int w = n * SSTR + k / 2;
                Bh[w] = h; Bl[w] = l;
            }
        }
        // ---- fused mask generation (every mw_every iters) ----
        if (mw_total) {
            const int cc = kc >> 5;
            if (cc % mw_every == 0) {
                const uint32_t w = gid + (uint32_t)(cc / mw_every) * mw_stride;
                if (w < mw_total) g_mask[w] = mask_word(w);
            }
        }
        __syncthreads();

#pragma unroll
        for (int ks = 0; ks < 2; ks++) {
            uint32_t ah[4][4], al[4][4];
#pragma unroll
            for (int mt = 0; mt < 4; mt++) {
                const uint32_t off =
                    (uint32_t)(((wy * 64 + mt * 16 + a_row) * SSTR) + ks * 8 + a_cw) * 4u;
                ldsm4(ah[mt], ahb + off);
                ldsm4(al[mt], alb + off);
            }
#pragma unroll
            for (int nt = 0; nt < 4; nt++) {
                const uint32_t off =
                    (uint32_t)(((wx * 32 + nt * 8 + b_row) * SSTR) + ks * 8 + b_cw) * 4u;
                uint32_t bh[2], bl[2];
                ldsm2(bh, bhb + off);
                ldsm2(bl, blb + off);
#pragma unroll
                for (int mt = 0; mt < 4; mt++) {
                    mma16816(acc[mt][nt], ah[mt], bh);
                    mma16816(acc[mt][nt], ah[mt], bl);
                    mma16816(acc[mt][nt], al[mt], bh);
                }
            }
        }
    }

#pragma unroll
    for (int mt = 0; mt < 4; mt++) {
        const int r0 = m0 + wy * 64 + mt * 16 + gq;
#pragma unroll
        for (int nt = 0; nt < 4; nt++) {
            const int col = n0 + wx * 32 + nt * 8 + gt * 2;
            float bx = 0.f, by = 0.f;
            if (has_bias) { bx = bias[col]; by = bias[col + 1]; }
            *reinterpret_cast<float2*>(C + (size_t)r0 * N + col) =
                make_float2(acc[mt][nt][0] + bx, acc[mt][nt][1] + by);
            *reinterpret_cast<float2*>(C + (size_t)(r0 + 8) * N + col) =
                make_float2(acc[mt][nt][2] + bx, acc[mt][nt][3] + by);
        }
    }
}

// ===========================================================================
//  fused Wq + Wkv launch: 1152 CTAs (384 Wq tiles + 768 Wkv tiles).
//  Mask spread across the whole grid: every 3rd iter, 8 emissions cover 2.1M.
// ===========================================================================
__global__ __launch_bounds__(256, 2) void fused_qkv(
    const float* __restrict__ Aq, const float* __restrict__ Wq_, float* __restrict__ Cq,
    const float* __restrict__ Ak, const float* __restrict__ Wkv_, float* __restrict__ Ckv)
{
    __shared__ uint32_t Ah[128 * SSTR];
    __shared__ uint32_t Al[128 * SSTR];
    __shared__ uint32_t Bh[128 * SSTR];
    __shared__ uint32_t Bl[128 * SSTR];

    const int tid = threadIdx.x;
    const int bid = blockIdx.x;
    const uint32_t gid = (uint32_t)bid * 256u + (uint32_t)tid;

    const float *A, *Bm;
    float* C;
    int N, m0, n0;
    if (bid < 384) {
        A = Aq; Bm = Wq_; C = Cq; N = 768;
        m0 = (bid / 6) * 128;  n0 = (bid % 6) * 128;
    } else {
        const int g = bid - 384;
        A = Ak; Bm = Wkv_; C = Ckv; N = 1536;
        m0 = (g / 12) * 128;   n0 = (g % 12) * 128;
    }
    gemm_body(A, Bm, nullptr, C, N, 768, m0, n0, tid,
              gid, 294912u, 2097152u, 3, Ah, Al, Bh, Bl, false);
}

// ===========================================================================
//  standalone gemm (Wproj, bias, no mask)
// ===========================================================================
__global__ __launch_bounds__(256, 2) void mma_gemm_b(
    const float* __restrict__ A, const float* __restrict__ Bm,
    const float* __restrict__ bias, float* __restrict__ C,
    int M, int N, int K)
{
    __shared__ uint32_t Ah[128 * SSTR];
    __shared__ uint32_t Al[128 * SSTR];
    __shared__ uint32_t Bh[128 * SSTR];
    __shared__ uint32_t Bl[128 * SSTR];
    gemm_body(A, Bm, bias, C, N, K, blockIdx.y * 128, blockIdx.x * 128,
              threadIdx.x, 0u, 0u, 0u, 1, Ah, Al, Bh, Bl, true);
}

// ===========================================================================
//  prep (round-13): pack Q (scaled) / K head-major hi-only; split V
// ===========================================================================
__global__ __launch_bounds__(256) void prep_kernel()
{
    __shared__ float vs[64 * 100];
    const int nt = blockIdx.x, bh = blockIdx.y;
    const int b = bh >> 3, h = bh & 7;
    const int tid = threadIdx.x;
    const int n0 = nt * 64;

#pragma unroll
    for (int p = 0; p < 6; p++) {
        const int idx = tid + p * 256;
        const int row = idx / 24, c4 = idx % 24;
        const size_t grow = (size_t)(b * 1024 + n0 + row);
        float4 qv = *reinterpret_cast<const float4*>(g_q + grow * 768 + h * 96 + c4 * 4);
        const size_t w = (size_t)(bh * 1024 + n0 + row) * 48 + c4 * 2;
        *reinterpret_cast<uint2*>(g_qh + w) =
            make_uint2(pack_hi(qv.x * QSCALE, qv.y * QSCALE),
                       pack_hi(qv.z * QSCALE, qv.w * QSCALE));
        const float* kg = g_kv + grow * 1536 + h * 96 + c4 * 4;
        float4 kv = *reinterpret_cast<const float4*>(kg);
        *reinterpret_cast<uint2*>(g_kh + w) =
            make_uint2(pack_hi(kv.x, kv.y), pack_hi(kv.z, kv.w));
        float4 vv = *reinterpret_cast<const float4*>(kg + 768);
        *reinterpret_cast<float4*>(&vs[row * 100 + c4 * 4]) = vv;
    }
    __syncthreads();
#pragma unroll
    for (int p = 0; p < 12; p++) {
        const int idx = tid + p * 256;
        const int d = idx >> 5, nw = idx & 31;
        float v0 = vs[(2 * nw) * 100 + d];
        float v1 = vs[(2 * nw + 1) * 100 + d];
        uint32_t hh, ll;
        split2(v0, v1, hh, ll);
        const size_t w = (size_t)(bh * 96 + d) * 512 + nt * 32 + nw;
        g_vth[w] = hh; g_vtl[w] = ll;
    }
}

// ===========================================================================
//  fused attention (round-13): QK hi-only both passes; PV 3-term; ldmatrix.
// ===========================================================================
constexpr int QSTR = 52;
constexpr int VSTR = 36;

DEV_INLINE void qk_mma_hi(uint32_t qhb, uint32_t khb,
                          int rowb, int lane, float (*sacc)[4])
{
    const int lt = lane >> 3, lr = lane & 7;
    const int a_row = ((lt & 1) << 3) + lr;
    const int a_cw  = (lt >> 1) << 2;
    const int b_row = lr;
    const int b_cw  = ((lane >> 3) & 1) << 2;
#pragma unroll
    for (int i = 0; i < 8; i++)
#pragma unroll
        for (int j = 0; j < 4; j++) sacc[i][j] = 0.f;
#pragma unroll
    for (int ks = 0; ks < 6; ks++) {
        uint32_t ah[4];
        const uint32_t aoff =
            (uint32_t)(((rowb + a_row) * QSTR) + ks * 8 + a_cw) * 4u;
        ldsm4(ah, qhb + aoff);
#pragma unroll
        for (int nt = 0; nt < 8; nt++) {
            const uint32_t boff =
                (uint32_t)(((nt * 8 + b_row) * QSTR) + ks * 8 + b_cw) * 4u;
            uint32_t bh2[2];
            ldsm2(bh2, khb + boff);
            mma16816(sacc[nt], ah, bh2);
        }
    }
}

DEV_INLINE void online_upd(float& m, float& z, float s) {
    float nm = fmaxf(m, s);
    z = z * __expf(m - nm) + __expf(s - nm);
    m = nm;
}
DEV_INLINE void comb_mz(float& m, float& z, int d) {
    float mo = __shfl_xor_sync(0xffffffffu, m, d);
    float zo = __shfl_xor_sync(0xffffffffu, z, d);
    float nm = fmaxf(m, mo);
    z = z * __expf(m - nm) + zo * __expf(mo - nm);
    m = nm;
}

__global__ __launch_bounds__(256, 2) void attn_mma()
{
    extern __shared__ uint32_t smw[];
    uint32_t* Qh = smw;
    uint32_t* Kh = Qh + 128 * QSTR;
    uint32_t* Vh = Kh + 64 * QSTR;
    uint32_t* Vl = Vh + 96 * VSTR;

    const int qt = blockIdx.x, bh = blockIdx.y;
    const int b = bh >> 3, h = bh & 7;
    const int tid = threadIdx.x, lane = tid & 31, wid = tid >> 5;
    const int gq = lane >> 2, gt = lane & 3;
    const int rowb = wid * 16;

    const uint32_t qhb = smem_u32(Qh);
    const uint32_t khb = smem_u32(Kh);
    const uint32_t vhb = smem_u32(Vh), vlb = smem_u32(Vl);

    {
        const uint4* qh4 = reinterpret_cast<const uint4*>(g_qh + (size_t)(bh * 1024 + qt * 128) * 48);
#pragma unroll
        for (int p = 0; p < 6; p++) {
            const int idx = tid + p * 256;
            const int row = idx / 12, s = idx % 12;
            *reinterpret_cast<uint4*>(&Qh[row * QSTR + s * 4]) = qh4[row * 12 + s];
        }
    }

    float m1[2] = {-1e30f, -1e30f}, z1[2] = {0.f, 0.f};
    float m2[2] = {-1e30f, -1e30f}, z2[2] = {0.f, 0.f};
    float sacc[8][4];

    // ---- PASS A: stats ----
    for (int c = 0; c < 16; c++) {
        __syncthreads();
        {
            const uint4* kh4 = reinterpret_cast<const uint4*>(g_kh + (size_t)(bh * 1024 + c * 64) * 48);
#pragma unroll
            for (int p = 0; p < 3; p++) {
                const int idx = tid + p * 256;
                const int row = idx / 12, s = idx % 12;
                *reinterpret_cast<uint4*>(&Kh[row * QSTR + s * 4]) = kh4[row * 12 + s];
            }
        }
        __syncthreads();
        qk_mma_hi(qhb, khb, rowb, lane, sacc);

        if (c == 0) {
#pragma unroll
            for (int nt = 0; nt < 8; nt++)
#pragma unroll
                for (int v = 0; v < 4; v++) {
                    const int col = nt * 8 + gt * 2 + (v & 1);
                    const int r = v >> 1;
                    if (col < 20) online_upd(m1[r], z1[r], sacc[nt][v]);
                    else          online_upd(m2[r], z2[r], sacc[nt][v]);
                }
        } else {
#pragma unroll
            for (int r = 0; r < 2; r++) {
                float lm = -1e30f;
#pragma unroll
                for (int nt = 0; nt < 8; nt++)
                    lm = fmaxf(lm, fmaxf(sacc[nt][r * 2], sacc[nt][r * 2 + 1]));
                const float nm = fmaxf(m2[r], lm);
                float zs = 0.f;
#pragma unroll
                for (int nt = 0; nt < 8; nt++)
                    zs += __expf(sacc[nt][r * 2] - nm) + __expf(sacc[nt][r * 2 + 1] - nm);
                z2[r] = z2[r] * __expf(m2[r] - nm) + zs;
                m2[r] = nm;
            }
        }
    }
#pragma unroll
    for (int r = 0; r < 2; r++) {
        comb_mz(m1[r], z1[r], 1); comb_mz(m1[r], z1[r], 2);
        comb_mz(m2[r], z2[r], 1); comb_mz(m2[r], z2[r], 2);
    }
    const float rz1[2] = {1.f / z1[0], 1.f / z1[1]};
    const float rz2[2] = {1.f / z2[0], 1.f / z2[1]};

    // ---- PASS B: hi-only QK recompute + mask + PV (3-term) ----
    float vacc[12][4];
#pragma unroll
    for (int i = 0; i < 12; i++)
#pragma unroll
        for (int j = 0; j < 4; j++) vacc[i][j] = 0.f;
    float zf[2] = {0.f, 0.f};
    const int q0 = qt * 128 + rowb + gq;
    const uint32_t* mrow = g_mask + ((size_t)(bh << 10) + q0) * 32;

    const int v_row = lane & 7;
    const int v_cw  = ((lane >> 3) & 1) << 2;

    for (int c = 0; c < 16; c++) {
        __syncthreads();
        {
            const uint4* kh4 = reinterpret_cast<const uint4*>(g_kh + (size_t)(bh * 1024 + c * 64) * 48);
#pragma unroll
            for (int p = 0; p < 3; p++) {
                const int idx = tid + p * 256;
                const int row = idx / 12, s = idx % 12;
                *reinterpret_cast<uint4*>(&Kh[row * QSTR + s * 4]) = kh4[row * 12 + s];
            }
            const uint4* vh4 = reinterpret_cast<const uint4*>(g_vth + (size_t)(bh * 96) * 512);
            const uint4* vl4 = reinterpret_cast<const uint4*>(g_vtl + (size_t)(bh * 96) * 512);
#pragma unroll
            for (int p = 0; p < 3; p++) {
                const int idx = tid + p * 256;
                const int row = idx >> 3, s = idx & 7;
                *reinterpret_cast<uint4*>(&Vh[row * VSTR + s * 4]) = vh4[row * 128 + c * 8 + s];
                *reinterpret_cast<uint4*>(&Vl[row * VSTR + s * 4]) = vl4[row * 128 + c * 8 + s];
            }
        }
        __syncthreads();
        qk_mma_hi(qhb, khb, rowb, lane, sacc);

        const uint32_t mw0 = mrow[c * 2];
        const uint32_t mw1 = mrow[c * 2 + 1];
        const uint32_t mw2 = mrow[8 * 32 + c * 2];
        const uint32_t mw3 = mrow[8 * 32 + c * 2 + 1];

#pragma unroll
        for (int ks = 0; ks < 4; ks++) {
            uint32_t pah[4], pal[4];
#pragma unroll
            for (int half = 0; half < 2; half++) {
                const int nt = 2 * ks + half;
                float e[4];
#pragma unroll
                for (int v = 0; v < 4; v++) {
                    const int co = nt * 8 + gt * 2 + (v & 1);
                    const int r = v >> 1;
                    const bool cls = (c == 0) && (co < 20);
                    const float m  = cls ? m1[r] : m2[r];
                    const float rz = cls ? rz1[r] : rz2[r];
                    const float a  = __expf(sacc[nt][v] - m) * rz;
                    const uint32_t wsel = (nt < 4) ? (r ? mw2 : mw0) : (r ? mw3 : mw1);
                    const uint32_t keep = (wsel >> (co & 31)) & 1u;
                    const float ev = keep ? __expf(a - 1.f) : 0.f;
                    e[v] = ev;
                    zf[r] += ev;
                }
                uint32_t hh, ll;
                split2(e[0], e[1], hh, ll);
                pah[half * 2] = hh;     pal[half * 2] = ll;
                split2(e[2], e[3], hh, ll);
                pah[half * 2 + 1] = hh; pal[half * 2 + 1] = ll;
            }
#pragma unroll
            for (int nt = 0; nt < 12; nt++) {
                const uint32_t off =
                    (uint32_t)(((nt * 8 + v_row) * VSTR) + ks * 8 + v_cw) * 4u;
                uint32_t bh2[2], bl2[2];
                ldsm2(bh2, vhb + off);
                ldsm2(bl2, vlb + off);
                mma16816(vacc[nt], pah, bh2);
                mma16816(vacc[nt], pah, bl2);
                mma16816(vacc[nt], pal, bh2);
            }
        }
    }

#pragma unroll
    for (int r = 0; r < 2; r++) {
        zf[r] += __shfl_xor_sync(0xffffffffu, zf[r], 1);
        zf[r] += __shfl_xor_sync(0xffffffffu, zf[r], 2);
    }
    const float r0 = 1.f / zf[0], r1 = 1.f / zf[1];
    float* og = g_ao + (size_t)(b * 1024 + q0) * 768 + h * 96;
#pragma unroll
    for (int nt = 0; nt < 12; nt++) {
        const int col = nt * 8 + gt * 2;
        *reinterpret_cast<float2*>(og + col) =
            make_float2(vacc[nt][0] * r0, vacc[nt][1] * r0);
        *reinterpret_cast<float2*>(og + 8 * 768 + col) =
            make_float2(vacc[nt][2] * r1, vacc[nt][3] * r1);
    }
}

// ---------------------------------------------------------------------------
extern "C" void kernel_launch(void* const* d_in, const int* in_sizes, int n_in,
                              void* d_out, int out_size)
{
    const float* input_query = (const float*)d_in[0];
    const float* input_key   = (const float*)d_in[1];
    const float* Wq          = (const float*)d_in[2];
    const float* Wkv         = (const float*)d_in[3];
    // d_in[4] = Wcls  -- provably unused
    const float* Wproj       = (const float*)d_in[5];
    const float* bproj       = (const float*)d_in[6];
    float* out = (float*)d_out;

    float *qp, *kvp, *aop;
    cudaGetSymbolAddress((void**)&qp,  g_q);
    cudaGetSymbolAddress((void**)&kvp, g_kv);
    cudaGetSymbolAddress((void**)&aop, g_ao);

    const int attn_smem = (128 * QSTR + 64 * QSTR + 96 * VSTR * 2) * 4; // ~68KB
    cudaFuncSetAttribute(attn_mma, cudaFuncAttributeMaxDynamicSharedMemorySize, attn_smem);

    // fused Wq (384 tiles) + Wkv (768 tiles), mask spread across whole grid
    fused_qkv<<<1152, 256>>>(input_query, Wq, qp, input_key, Wkv, kvp);
    prep_kernel<<<dim3(16, 64), 256>>>();
    attn_mma<<<dim3(8, 64), 256, attn_smem>>>();
    mma_gemm_b<<<dim3(6, 64), 256>>>(aop, Wproj, bproj, out, 8192, 768, 768);
}